// round 1
// baseline (speedup 1.0000x reference)
#include <cuda_runtime.h>
#include <cuda_bf16.h>

#define NN 50000
#define FE 128
#define NE 640000
#define MT 64           // GEMM M tile
#define XS (FE + 4)     // padded Xs row stride (avoid bank conflicts)

// Scratch (allocation-free rule: __device__ globals)
__device__ float d_Y[(size_t)NN * FE];    // X @ W
__device__ float d_agg[(size_t)NN * FE];  // segment sums of Y[src]
__device__ int   d_cnt[NN];               // segment counts

// ---------------------------------------------------------------------------
// Zero the aggregation scratch (out is poisoned; agg/cnt must start at 0)
// ---------------------------------------------------------------------------
__global__ void zero_kernel() {
    int i = blockIdx.x * blockDim.x + threadIdx.x;
    if (i < NN * FE / 4) ((float4*)d_agg)[i] = make_float4(0.f, 0.f, 0.f, 0.f);
    if (i < NN) d_cnt[i] = 0;
}

// ---------------------------------------------------------------------------
// Y = X @ W  (K = N = 128 fixed). W fully staged in SMEM (64KB), 64-row X
// tile (padded), each thread computes a 4x8 register block.
// Epilogue: write Y to scratch AND relu(Y) to out[:, 0:128].
// ---------------------------------------------------------------------------
__global__ __launch_bounds__(256, 2)
void gemm_relu_kernel(const float* __restrict__ X, const float* __restrict__ W,
                      float* __restrict__ out) {
    extern __shared__ float sm[];
    float* Ws = sm;               // [128][128]
    float* Xs = sm + FE * FE;     // [64][132]

    const int tid  = threadIdx.x;
    const int row0 = blockIdx.x * MT;

    // Load W (128x128 fp32 = 16384 floats = 4096 float4 / 256 threads = 16 each)
    #pragma unroll
    for (int i = 0; i < 16; ++i) {
        int idx = i * 256 + tid;
        ((float4*)Ws)[idx] = ((const float4*)W)[idx];
    }
    // Load X tile (64x128 = 2048 float4 / 256 threads = 8 each), zero-pad OOB rows
    #pragma unroll
    for (int i = 0; i < 8; ++i) {
        int idx = i * 256 + tid;
        int r   = idx >> 5;          // / (FE/4)
        int c4  = idx & 31;
        float4 v = make_float4(0.f, 0.f, 0.f, 0.f);
        if (row0 + r < NN) v = ((const float4*)X)[(size_t)(row0 + r) * (FE / 4) + c4];
        *(float4*)&Xs[r * XS + c4 * 4] = v;
    }
    __syncthreads();

    const int r0 = (tid >> 4) * 4;   // 16 row groups of 4
    const int c0 = (tid & 15) * 8;   // 16 col groups of 8

    float acc[4][8];
    #pragma unroll
    for (int i = 0; i < 4; ++i)
        #pragma unroll
        for (int j = 0; j < 8; ++j) acc[i][j] = 0.f;

    #pragma unroll 8
    for (int k = 0; k < FE; ++k) {
        float a0 = Xs[(r0 + 0) * XS + k];
        float a1 = Xs[(r0 + 1) * XS + k];
        float a2 = Xs[(r0 + 2) * XS + k];
        float a3 = Xs[(r0 + 3) * XS + k];
        float4 b0 = *(const float4*)&Ws[k * FE + c0];
        float4 b1 = *(const float4*)&Ws[k * FE + c0 + 4];
        float b[8] = {b0.x, b0.y, b0.z, b0.w, b1.x, b1.y, b1.z, b1.w};
        #pragma unroll
        for (int j = 0; j < 8; ++j) {
            acc[0][j] = fmaf(a0, b[j], acc[0][j]);
            acc[1][j] = fmaf(a1, b[j], acc[1][j]);
            acc[2][j] = fmaf(a2, b[j], acc[2][j]);
            acc[3][j] = fmaf(a3, b[j], acc[3][j]);
        }
    }

    #pragma unroll
    for (int i = 0; i < 4; ++i) {
        int r = row0 + r0 + i;
        if (r < NN) {
            float4 y0 = make_float4(acc[i][0], acc[i][1], acc[i][2], acc[i][3]);
            float4 y1 = make_float4(acc[i][4], acc[i][5], acc[i][6], acc[i][7]);
            // raw Y for the scatter pass
            *(float4*)&d_Y[(size_t)r * FE + c0]     = y0;
            *(float4*)&d_Y[(size_t)r * FE + c0 + 4] = y1;
            // relu(Y) -> out[:, 0:128]
            float4 o0 = make_float4(fmaxf(y0.x, 0.f), fmaxf(y0.y, 0.f),
                                    fmaxf(y0.z, 0.f), fmaxf(y0.w, 0.f));
            float4 o1 = make_float4(fmaxf(y1.x, 0.f), fmaxf(y1.y, 0.f),
                                    fmaxf(y1.z, 0.f), fmaxf(y1.w, 0.f));
            *(float4*)&out[(size_t)r * 256 + c0]     = o0;
            *(float4*)&out[(size_t)r * 256 + c0 + 4] = o1;
        }
    }
}

// ---------------------------------------------------------------------------
// Scatter: one warp per edge. Gather Y[src] (512B, one float4 per lane) and
// red.global.add.v4.f32 into d_agg[dst]. Lane 0 bumps the count.
// ---------------------------------------------------------------------------
__global__ void scatter_kernel(const int* __restrict__ edst,
                               const int* __restrict__ esrc) {
    int g    = blockIdx.x * blockDim.x + threadIdx.x;
    int e    = g >> 5;
    int lane = g & 31;
    if (e >= NE) return;
    int s = esrc[e];
    int d = edst[e];
    float4 v = ((const float4*)(d_Y + (size_t)s * FE))[lane];
    float* p = d_agg + (size_t)d * FE + lane * 4;
    asm volatile("red.global.add.v4.f32 [%0], {%1, %2, %3, %4};"
                 :: "l"(p), "f"(v.x), "f"(v.y), "f"(v.z), "f"(v.w)
                 : "memory");
    if (lane == 0) atomicAdd(&d_cnt[d], 1);
}

// ---------------------------------------------------------------------------
// Combine: out[:, 128:256] = relu(agg / max(cnt,1)). (cnt==0 -> agg==0 -> 0.)
// ---------------------------------------------------------------------------
__global__ void combine_kernel(float* __restrict__ out) {
    int idx = blockIdx.x * blockDim.x + threadIdx.x;   // over NN * 32 float4s
    if (idx >= NN * FE / 4) return;
    int n  = idx >> 5;
    int c4 = idx & 31;
    int c  = d_cnt[n];
    float inv = 1.0f / (float)(c > 1 ? c : 1);
    float4 s = ((const float4*)d_agg)[idx];
    float4 r = make_float4(fmaxf(s.x * inv, 0.f), fmaxf(s.y * inv, 0.f),
                           fmaxf(s.z * inv, 0.f), fmaxf(s.w * inv, 0.f));
    ((float4*)(out + (size_t)n * 256 + 128))[c4] = r;
}

// ---------------------------------------------------------------------------
extern "C" void kernel_launch(void* const* d_in, const int* in_sizes, int n_in,
                              void* d_out, int out_size) {
    const float* X    = (const float*)d_in[0];  // features [NN, 128]
    const float* W    = (const float*)d_in[1];  // weight   [128, 128]
    const int*   edst = (const int*)d_in[2];    // edges_dst [NE]
    const int*   esrc = (const int*)d_in[3];    // edges_src [NE]
    float*       out  = (float*)d_out;          // [NN, 256]

    const int smem_bytes = (FE * FE + MT * XS) * (int)sizeof(float);  // ~97KB
    cudaFuncSetAttribute(gemm_relu_kernel,
                         cudaFuncAttributeMaxDynamicSharedMemorySize, smem_bytes);

    zero_kernel<<<(NN * FE / 4 + 255) / 256, 256>>>();
    gemm_relu_kernel<<<(NN + MT - 1) / MT, 256, smem_bytes>>>(X, W, out);
    scatter_kernel<<<(NE * 32 + 255) / 256, 256>>>(edst, esrc);
    combine_kernel<<<(NN * FE / 4 + 255) / 256, 256>>>(out);
}

// round 2
// speedup vs baseline: 1.0043x; 1.0043x over previous
#include <cuda_runtime.h>
#include <cuda_bf16.h>

#define NN 50000
#define FE 128
#define NE 640000
#define MT 64            // GEMM M tile
#define XT 68            // transposed X tile stride (64 rows + pad, 16B-aligned)

// Scratch (allocation-free rule: __device__ globals)
__device__ float d_Y[(size_t)NN * FE];  // X @ W
__device__ int   d_cnt[NN];             // in-degree
__device__ int   d_off[NN];             // CSR offsets (exclusive scan)
__device__ int   d_cur[NN];             // fill cursors
__device__ int   d_srcl[NE];            // bucketed source node ids

// ---------------------------------------------------------------------------
__global__ void zero_cnt_kernel() {
    int i = blockIdx.x * blockDim.x + threadIdx.x;
    if (i < NN) d_cnt[i] = 0;
}

// hist of edges_dst
__global__ void hist_kernel(const int* __restrict__ edst) {
    int e = blockIdx.x * blockDim.x + threadIdx.x;
    if (e < NE) atomicAdd(&d_cnt[edst[e]], 1);
}

// single-block exclusive scan of d_cnt -> d_off (+ copy to d_cur)
__global__ void scan_kernel() {
    __shared__ int wsum[32];
    __shared__ int carry;
    const int tid = threadIdx.x;
    const int lane = tid & 31, wid = tid >> 5;
    if (tid == 0) carry = 0;
    __syncthreads();
    for (int base = 0; base < NN; base += 1024) {
        int i = base + tid;
        int x = (i < NN) ? d_cnt[i] : 0;
        int v = x;
        #pragma unroll
        for (int o = 1; o < 32; o <<= 1) {
            int t = __shfl_up_sync(0xffffffffu, v, o);
            if (lane >= o) v += t;
        }
        if (lane == 31) wsum[wid] = v;
        __syncthreads();
        if (tid < 32) {
            int s = wsum[tid];
            int sv = s;
            #pragma unroll
            for (int o = 1; o < 32; o <<= 1) {
                int t = __shfl_up_sync(0xffffffffu, sv, o);
                if (tid >= o) sv += t;
            }
            wsum[tid] = sv - s;   // exclusive warp prefix
        }
        __syncthreads();
        int excl = carry + wsum[wid] + (v - x);
        if (i < NN) { d_off[i] = excl; d_cur[i] = excl; }
        __syncthreads();
        if (tid == 1023) carry = excl + x;   // = old carry + chunk total
        __syncthreads();
    }
}

// bucket source ids by dst
__global__ void fill_kernel(const int* __restrict__ edst,
                            const int* __restrict__ esrc) {
    int e = blockIdx.x * blockDim.x + threadIdx.x;
    if (e >= NE) return;
    int d = edst[e];
    int slot = atomicAdd(&d_cur[d], 1);
    d_srcl[slot] = esrc[e];
}

// ---------------------------------------------------------------------------
// Y = X @ W. W fully staged in SMEM; X tile stored TRANSPOSED so the 4 A
// operands come from a single LDS.128 (broadcast within the warp).
// Epilogue: Y -> scratch, relu(Y) -> out[:, 0:128].
// ---------------------------------------------------------------------------
__global__ __launch_bounds__(256, 2)
void gemm_relu_kernel(const float* __restrict__ X, const float* __restrict__ W,
                      float* __restrict__ out) {
    extern __shared__ float sm[];
    float* Ws  = sm;              // [128][128]
    float* XsT = sm + FE * FE;    // [128][68]  (k-major, transposed)

    const int tid  = threadIdx.x;
    const int row0 = blockIdx.x * MT;

    #pragma unroll
    for (int i = 0; i < 16; ++i) {
        int idx = i * 256 + tid;
        ((float4*)Ws)[idx] = ((const float4*)W)[idx];
    }
    #pragma unroll
    for (int i = 0; i < 8; ++i) {
        int idx = i * 256 + tid;          // over 2048 float4s of the X tile
        int r   = idx >> 5;
        int c4  = idx & 31;
        float4 v = make_float4(0.f, 0.f, 0.f, 0.f);
        if (row0 + r < NN) v = ((const float4*)X)[(size_t)(row0 + r) * (FE / 4) + c4];
        XsT[(c4 * 4 + 0) * XT + r] = v.x;
        XsT[(c4 * 4 + 1) * XT + r] = v.y;
        XsT[(c4 * 4 + 2) * XT + r] = v.z;
        XsT[(c4 * 4 + 3) * XT + r] = v.w;
    }
    __syncthreads();

    const int r0 = (tid >> 4) * 4;
    const int c0 = (tid & 15) * 8;

    float acc[4][8];
    #pragma unroll
    for (int i = 0; i < 4; ++i)
        #pragma unroll
        for (int j = 0; j < 8; ++j) acc[i][j] = 0.f;

    #pragma unroll 8
    for (int k = 0; k < FE; ++k) {
        float4 a  = *(const float4*)&XsT[k * XT + r0];
        float4 b0 = *(const float4*)&Ws[k * FE + c0];
        float4 b1 = *(const float4*)&Ws[k * FE + c0 + 4];
        float av[4] = {a.x, a.y, a.z, a.w};
        float bv[8] = {b0.x, b0.y, b0.z, b0.w, b1.x, b1.y, b1.z, b1.w};
        #pragma unroll
        for (int i = 0; i < 4; ++i)
            #pragma unroll
            for (int j = 0; j < 8; ++j)
                acc[i][j] = fmaf(av[i], bv[j], acc[i][j]);
    }

    #pragma unroll
    for (int i = 0; i < 4; ++i) {
        int r = row0 + r0 + i;
        if (r < NN) {
            float4 y0 = make_float4(acc[i][0], acc[i][1], acc[i][2], acc[i][3]);
            float4 y1 = make_float4(acc[i][4], acc[i][5], acc[i][6], acc[i][7]);
            *(float4*)&d_Y[(size_t)r * FE + c0]     = y0;
            *(float4*)&d_Y[(size_t)r * FE + c0 + 4] = y1;
            float4 o0 = make_float4(fmaxf(y0.x, 0.f), fmaxf(y0.y, 0.f),
                                    fmaxf(y0.z, 0.f), fmaxf(y0.w, 0.f));
            float4 o1 = make_float4(fmaxf(y1.x, 0.f), fmaxf(y1.y, 0.f),
                                    fmaxf(y1.z, 0.f), fmaxf(y1.w, 0.f));
            *(float4*)&out[(size_t)r * 256 + c0]     = o0;
            *(float4*)&out[(size_t)r * 256 + c0 + 4] = o1;
        }
    }
}

// ---------------------------------------------------------------------------
// Atomic-free aggregation: one warp per dst node. Gather Y[src] rows for its
// edge list, accumulate one float4/lane, write relu(sum/deg) to out[:,128:].
// ---------------------------------------------------------------------------
__global__ __launch_bounds__(256)
void agg_kernel(float* __restrict__ out) {
    int g    = blockIdx.x * blockDim.x + threadIdx.x;
    int n    = g >> 5;
    int lane = g & 31;
    if (n >= NN) return;

    int deg  = d_cnt[n];
    int base = d_off[n];
    float4 acc = make_float4(0.f, 0.f, 0.f, 0.f);

    int i = 0;
    for (; i + 4 <= deg; i += 4) {
        int s0 = d_srcl[base + i + 0];
        int s1 = d_srcl[base + i + 1];
        int s2 = d_srcl[base + i + 2];
        int s3 = d_srcl[base + i + 3];
        float4 v0 = ((const float4*)(d_Y + (size_t)s0 * FE))[lane];
        float4 v1 = ((const float4*)(d_Y + (size_t)s1 * FE))[lane];
        float4 v2 = ((const float4*)(d_Y + (size_t)s2 * FE))[lane];
        float4 v3 = ((const float4*)(d_Y + (size_t)s3 * FE))[lane];
        acc.x += v0.x + v1.x + v2.x + v3.x;
        acc.y += v0.y + v1.y + v2.y + v3.y;
        acc.z += v0.z + v1.z + v2.z + v3.z;
        acc.w += v0.w + v1.w + v2.w + v3.w;
    }
    for (; i < deg; ++i) {
        int s = d_srcl[base + i];
        float4 v = ((const float4*)(d_Y + (size_t)s * FE))[lane];
        acc.x += v.x; acc.y += v.y; acc.z += v.z; acc.w += v.w;
    }

    float inv = (deg > 0) ? (1.0f / (float)deg) : 0.0f;
    float4 r = make_float4(fmaxf(acc.x * inv, 0.f), fmaxf(acc.y * inv, 0.f),
                           fmaxf(acc.z * inv, 0.f), fmaxf(acc.w * inv, 0.f));
    ((float4*)(out + (size_t)n * 256 + 128))[lane] = r;
}

// ---------------------------------------------------------------------------
extern "C" void kernel_launch(void* const* d_in, const int* in_sizes, int n_in,
                              void* d_out, int out_size) {
    const float* X    = (const float*)d_in[0];
    const float* W    = (const float*)d_in[1];
    const int*   edst = (const int*)d_in[2];
    const int*   esrc = (const int*)d_in[3];
    float*       out  = (float*)d_out;

    const int smem_bytes = (FE * FE + FE * XT) * (int)sizeof(float);  // ~98KB
    cudaFuncSetAttribute(gemm_relu_kernel,
                         cudaFuncAttributeMaxDynamicSharedMemorySize, smem_bytes);

    zero_cnt_kernel<<<(NN + 255) / 256, 256>>>();
    hist_kernel<<<(NE + 255) / 256, 256>>>(edst);
    scan_kernel<<<1, 1024>>>();
    fill_kernel<<<(NE + 255) / 256, 256>>>(edst, esrc);
    gemm_relu_kernel<<<(NN + MT - 1) / MT, 256, smem_bytes>>>(X, W, out);
    agg_kernel<<<(NN * 32 + 255) / 256, 256>>>(out);
}

// round 4
// speedup vs baseline: 2.0308x; 2.0221x over previous
#include <cuda_runtime.h>
#include <cuda_bf16.h>
#include <cstdint>

#define NN 50000
#define FE 128
#define NE 640000
#define GT 128            // GEMM tile rows per CTA
#define ST 68             // padded SMEM row stride (u32 units) — conflict-free

// ---------------------------------------------------------------------------
// Scratch (__device__ globals: allocation-free rule)
// ---------------------------------------------------------------------------
__device__ float    d_Y[(size_t)NN * FE];   // X @ W (fp32)
__device__ int      d_cnt[NN];              // in-degree
__device__ int      d_off[NN];              // CSR offsets
__device__ int      d_cur[NN];              // fill cursors
__device__ int      d_srcl[NE];             // bucketed src ids
__device__ int      d_bsum[64];             // scan block sums
// W^T as packed bf16 k-pairs: d_Wh/d_Wl[n*64 + kp] = {bf16(W[2kp][n]), bf16(W[2kp+1][n])}
__device__ uint32_t d_Wh[FE * (FE / 2)];
__device__ uint32_t d_Wl[FE * (FE / 2)];

// ---------------------------------------------------------------------------
// bf16 helpers
// ---------------------------------------------------------------------------
__device__ __forceinline__ void split_pair(float f0, float f1,
                                           uint32_t& hi, uint32_t& lo) {
    __nv_bfloat162 h2 = __floats2bfloat162_rn(f0, f1);
    float h0 = __bfloat162float(h2.x), h1 = __bfloat162float(h2.y);
    __nv_bfloat162 l2 = __floats2bfloat162_rn(f0 - h0, f1 - h1);
    hi = *(uint32_t*)&h2;
    lo = *(uint32_t*)&l2;
}

// mma.sync m16n8k16 row.col f32.bf16.bf16.f32, accumulate in place
__device__ __forceinline__ void mma16816(float* c,
                                         uint32_t a0, uint32_t a1, uint32_t a2, uint32_t a3,
                                         uint32_t b0, uint32_t b1) {
    asm volatile(
        "mma.sync.aligned.m16n8k16.row.col.f32.bf16.bf16.f32 "
        "{%0,%1,%2,%3}, {%4,%5,%6,%7}, {%8,%9}, {%0,%1,%2,%3};"
        : "+f"(c[0]), "+f"(c[1]), "+f"(c[2]), "+f"(c[3])
        : "r"(a0), "r"(a1), "r"(a2), "r"(a3), "r"(b0), "r"(b1));
}

// ---------------------------------------------------------------------------
// prep: blocks 0..7 convert W -> bf16 hi/lo pair images; blocks 8.. zero d_cnt
// ---------------------------------------------------------------------------
__global__ void prep_kernel(const float* __restrict__ W) {
    int b = blockIdx.x, tid = threadIdx.x;
    if (b < 8) {
        int i = b * 1024 + tid;            // 8192 items
        int n = i >> 6, kp = i & 63;
        float w0 = W[(2 * kp)     * FE + n];
        float w1 = W[(2 * kp + 1) * FE + n];
        uint32_t hi, lo;
        split_pair(w0, w1, hi, lo);
        d_Wh[i] = hi;
        d_Wl[i] = lo;
    } else {
        int i = (b - 8) * 1024 + tid;
        if (i < NN) d_cnt[i] = 0;
    }
}

// ---------------------------------------------------------------------------
// CSR build
// ---------------------------------------------------------------------------
__global__ void hist_kernel(const int* __restrict__ edst) {
    int i = blockIdx.x * blockDim.x + threadIdx.x;
    if (i < NE / 4) {
        int4 d = ((const int4*)edst)[i];
        atomicAdd(&d_cnt[d.x], 1);
        atomicAdd(&d_cnt[d.y], 1);
        atomicAdd(&d_cnt[d.z], 1);
        atomicAdd(&d_cnt[d.w], 1);
    }
}

__global__ void scan1_kernel() {
    __shared__ int wsum[32];
    const int tid = threadIdx.x, lane = tid & 31, wid = tid >> 5;
    int i = blockIdx.x * 1024 + tid;
    int x = (i < NN) ? d_cnt[i] : 0;
    int v = x;
    #pragma unroll
    for (int o = 1; o < 32; o <<= 1) {
        int t = __shfl_up_sync(0xffffffffu, v, o);
        if (lane >= o) v += t;
    }
    if (lane == 31) wsum[wid] = v;
    __syncthreads();
    if (tid < 32) {
        int s = wsum[tid];
        int sv = s;
        #pragma unroll
        for (int o = 1; o < 32; o <<= 1) {
            int t = __shfl_up_sync(0xffffffffu, sv, o);
            if (tid >= o) sv += t;
        }
        wsum[tid] = sv - s;
        if (tid == 31) d_bsum[blockIdx.x] = sv;
    }
    __syncthreads();
    if (i < NN) d_off[i] = wsum[wid] + (v - x);
}

// parallel scan of <=64 block sums (fixes round-3 serial-latency bug)
__global__ void scan2_kernel(int nblk) {
    __shared__ int w0tot;
    int t = threadIdx.x;                 // 64 threads
    int lane = t & 31, w = t >> 5;
    int v = (t < nblk) ? d_bsum[t] : 0;
    int s = v;
    #pragma unroll
    for (int o = 1; o < 32; o <<= 1) {
        int x = __shfl_up_sync(0xffffffffu, s, o);
        if (lane >= o) s += x;
    }
    if (t == 31) w0tot = s;
    __syncthreads();
    int excl = s - v + (w ? w0tot : 0);
    if (t < nblk) d_bsum[t] = excl;
}

__global__ void scan3_kernel() {
    int i = blockIdx.x * 1024 + threadIdx.x;
    if (i < NN) {
        int v = d_off[i] + d_bsum[blockIdx.x];
        d_off[i] = v;
        d_cur[i] = v;
    }
}

__global__ void fill_kernel(const int* __restrict__ edst,
                            const int* __restrict__ esrc) {
    int i = blockIdx.x * blockDim.x + threadIdx.x;
    if (i < NE / 4) {
        int4 d = ((const int4*)edst)[i];
        int4 s = ((const int4*)esrc)[i];
        d_srcl[atomicAdd(&d_cur[d.x], 1)] = s.x;
        d_srcl[atomicAdd(&d_cur[d.y], 1)] = s.y;
        d_srcl[atomicAdd(&d_cur[d.z], 1)] = s.z;
        d_srcl[atomicAdd(&d_cur[d.w], 1)] = s.w;
    }
}

// ---------------------------------------------------------------------------
// GEMM via mma.sync bf16 3-term split. 256 thr (8 warps), 128-row tile.
// Warp w owns rows [w*16, w*16+16). Per warp: 16 n-blocks of m16n8, K=128.
// SMEM images (u32, stride ST=68): Xh, Xl (A pairs), Wh, Wl (B pairs).
// ---------------------------------------------------------------------------
#define XH_OFF 0
#define XL_OFF 8704
#define WH_OFF 17408
#define WL_OFF 26112
#define SM_U32 34816
#define SM_BYTES (SM_U32 * 4)

__global__ __launch_bounds__(256, 1)
void gemm_tc_kernel(const float* __restrict__ X, float* __restrict__ out) {
    extern __shared__ uint32_t smu[];
    const int tid  = threadIdx.x;
    const int wid  = tid >> 5, lane = tid & 31;
    const int g    = lane >> 2, tig = lane & 3;
    const int row0 = blockIdx.x * GT;

    // Stage W images (8192 u32 each) as uint4
    {
        const uint4* gh = (const uint4*)d_Wh;
        const uint4* gl = (const uint4*)d_Wl;
        #pragma unroll
        for (int i = 0; i < 8; ++i) {
            int q  = i * 256 + tid;          // 2048 uint4
            int n  = q >> 4, kq = q & 15;
            uint32_t o = n * ST + kq * 4;
            *(uint4*)&smu[WH_OFF + o] = gh[q];
            *(uint4*)&smu[WL_OFF + o] = gl[q];
        }
    }
    // Stage X tile: load fp32, split to bf16 hi/lo pairs
    #pragma unroll
    for (int i = 0; i < 16; ++i) {
        int q  = i * 256 + tid;              // 4096 float4
        int r  = q >> 5, c4 = q & 31;
        float4 v = make_float4(0.f, 0.f, 0.f, 0.f);
        if (row0 + r < NN) v = ((const float4*)X)[(size_t)(row0 + r) * 32 + c4];
        uint32_t h01, l01, h23, l23;
        split_pair(v.x, v.y, h01, l01);
        split_pair(v.z, v.w, h23, l23);
        uint32_t o = r * ST + c4 * 2;
        smu[XH_OFF + o]     = h01;
        smu[XH_OFF + o + 1] = h23;
        smu[XL_OFF + o]     = l01;
        smu[XL_OFF + o + 1] = l23;
    }
    __syncthreads();

    const int rw = wid * 16;
    float acc[16][4];
    #pragma unroll
    for (int j = 0; j < 16; ++j)
        #pragma unroll
        for (int q = 0; q < 4; ++q) acc[j][q] = 0.f;

    #pragma unroll
    for (int ks = 0; ks < 8; ++ks) {
        const int kb = ks * 8;
        uint32_t aRow0 = (rw + g)     * ST + kb + tig;
        uint32_t aRow8 = (rw + g + 8) * ST + kb + tig;
        uint32_t ah0 = smu[XH_OFF + aRow0];
        uint32_t ah1 = smu[XH_OFF + aRow8];
        uint32_t ah2 = smu[XH_OFF + aRow0 + 4];
        uint32_t ah3 = smu[XH_OFF + aRow8 + 4];
        uint32_t al0 = smu[XL_OFF + aRow0];
        uint32_t al1 = smu[XL_OFF + aRow8];
        uint32_t al2 = smu[XL_OFF + aRow0 + 4];
        uint32_t al3 = smu[XL_OFF + aRow8 + 4];
        #pragma unroll
        for (int j = 0; j < 16; ++j) {
            uint32_t bo  = (j * 8 + g) * ST + kb + tig;
            uint32_t bh0 = smu[WH_OFF + bo];
            uint32_t bh1 = smu[WH_OFF + bo + 4];
            uint32_t bl0 = smu[WL_OFF + bo];
            uint32_t bl1 = smu[WL_OFF + bo + 4];
            mma16816(acc[j], ah0, ah1, ah2, ah3, bh0, bh1);  // Ah*Bh
            mma16816(acc[j], ah0, ah1, ah2, ah3, bl0, bl1);  // Ah*Bl
            mma16816(acc[j], al0, al1, al2, al3, bh0, bh1);  // Al*Bh
        }
    }

    // Epilogue: Y -> scratch, relu(Y) -> out[:, 0:128]
    int r0g = row0 + rw + g;
    #pragma unroll
    for (int j = 0; j < 16; ++j) {
        int col = j * 8 + tig * 2;
        #pragma unroll
        for (int h = 0; h < 2; ++h) {
            int r = r0g + h * 8;
            if (r < NN) {
                float y0 = acc[j][h * 2], y1 = acc[j][h * 2 + 1];
                *(float2*)&d_Y[(size_t)r * FE + col] = make_float2(y0, y1);
                *(float2*)&out[(size_t)r * 256 + col] =
                    make_float2(fmaxf(y0, 0.f), fmaxf(y1, 0.f));
            }
        }
    }
}

// ---------------------------------------------------------------------------
// Atomic-free aggregation: one warp per dst node
// ---------------------------------------------------------------------------
__global__ __launch_bounds__(256)
void agg_kernel(float* __restrict__ out) {
    int g    = blockIdx.x * blockDim.x + threadIdx.x;
    int n    = g >> 5;
    int lane = g & 31;
    if (n >= NN) return;

    int deg  = d_cnt[n];
    int base = d_off[n];
    float4 acc = make_float4(0.f, 0.f, 0.f, 0.f);

    int i = 0;
    for (; i + 4 <= deg; i += 4) {
        int s0 = d_srcl[base + i + 0];
        int s1 = d_srcl[base + i + 1];
        int s2 = d_srcl[base + i + 2];
        int s3 = d_srcl[base + i + 3];
        float4 v0 = ((const float4*)(d_Y + (size_t)s0 * FE))[lane];
        float4 v1 = ((const float4*)(d_Y + (size_t)s1 * FE))[lane];
        float4 v2 = ((const float4*)(d_Y + (size_t)s2 * FE))[lane];
        float4 v3 = ((const float4*)(d_Y + (size_t)s3 * FE))[lane];
        acc.x += v0.x + v1.x + v2.x + v3.x;
        acc.y += v0.y + v1.y + v2.y + v3.y;
        acc.z += v0.z + v1.z + v2.z + v3.z;
        acc.w += v0.w + v1.w + v2.w + v3.w;
    }
    for (; i < deg; ++i) {
        int s = d_srcl[base + i];
        float4 v = ((const float4*)(d_Y + (size_t)s * FE))[lane];
        acc.x += v.x; acc.y += v.y; acc.z += v.z; acc.w += v.w;
    }

    float inv = (deg > 0) ? (1.0f / (float)deg) : 0.0f;
    float4 r = make_float4(fmaxf(acc.x * inv, 0.f), fmaxf(acc.y * inv, 0.f),
                           fmaxf(acc.z * inv, 0.f), fmaxf(acc.w * inv, 0.f));
    ((float4*)(out + (size_t)n * 256 + 128))[lane] = r;
}

// ---------------------------------------------------------------------------
extern "C" void kernel_launch(void* const* d_in, const int* in_sizes, int n_in,
                              void* d_out, int out_size) {
    const float* X    = (const float*)d_in[0];
    const float* W    = (const float*)d_in[1];
    const int*   edst = (const int*)d_in[2];
    const int*   esrc = (const int*)d_in[3];
    float*       out  = (float*)d_out;

    const int nscan = (NN + 1023) / 1024;  // 49

    cudaFuncSetAttribute(gemm_tc_kernel,
                         cudaFuncAttributeMaxDynamicSharedMemorySize, SM_BYTES);

    prep_kernel<<<8 + nscan, 1024>>>(W);
    hist_kernel<<<(NE / 4 + 255) / 256, 256>>>(edst);
    scan1_kernel<<<nscan, 1024>>>();
    scan2_kernel<<<1, 64>>>(nscan);
    scan3_kernel<<<nscan, 1024>>>();
    fill_kernel<<<(NE / 4 + 255) / 256, 256>>>(edst, esrc);
    gemm_tc_kernel<<<(NN + GT - 1) / GT, 256, SM_BYTES>>>(X, out);
    agg_kernel<<<(NN * 32 + 255) / 256, 256>>>(out);
}

// round 5
// speedup vs baseline: 2.0768x; 1.0227x over previous
#include <cuda_runtime.h>
#include <cuda_bf16.h>
#include <cstdint>

#define NN 50000
#define FE 128
#define NE 640000
#define GT 128            // GEMM tile rows per CTA
#define ST 68             // padded SMEM row stride (u32 units) — conflict-free

#define NSCAN 49          // ceil(NN/1024)
#define AFLAG (1 << 24)
#define PFLAG (1 << 25)
#define VMASK 0x00FFFFFF

// ---------------------------------------------------------------------------
// Scratch (__device__ globals: allocation-free rule)
// ---------------------------------------------------------------------------
__device__ float    d_Y[(size_t)NN * FE];   // X @ W (fp32)
__device__ int      d_cnt[NN];              // in-degree
__device__ int      d_off[NN];              // CSR offsets
__device__ int      d_cur[NN];              // fill cursors
__device__ int      d_srcl[NE];             // bucketed src ids
__device__ int      d_stat[64];             // lookback scan status
__device__ uint32_t d_Wh[FE * (FE / 2)];    // W^T bf16-hi k-pairs
__device__ uint32_t d_Wl[FE * (FE / 2)];    // W^T bf16-lo k-pairs

// ---------------------------------------------------------------------------
__device__ __forceinline__ void split_pair(float f0, float f1,
                                           uint32_t& hi, uint32_t& lo) {
    __nv_bfloat162 h2 = __floats2bfloat162_rn(f0, f1);
    float h0 = __bfloat162float(h2.x), h1 = __bfloat162float(h2.y);
    __nv_bfloat162 l2 = __floats2bfloat162_rn(f0 - h0, f1 - h1);
    hi = *(uint32_t*)&h2;
    lo = *(uint32_t*)&l2;
}

__device__ __forceinline__ void mma16816(float* c,
                                         uint32_t a0, uint32_t a1, uint32_t a2, uint32_t a3,
                                         uint32_t b0, uint32_t b1) {
    asm volatile(
        "mma.sync.aligned.m16n8k16.row.col.f32.bf16.bf16.f32 "
        "{%0,%1,%2,%3}, {%4,%5,%6,%7}, {%8,%9}, {%0,%1,%2,%3};"
        : "+f"(c[0]), "+f"(c[1]), "+f"(c[2]), "+f"(c[3])
        : "r"(a0), "r"(a1), "r"(a2), "r"(a3), "r"(b0), "r"(b1));
}

// ---------------------------------------------------------------------------
// prep: blocks 0..7 convert W; blocks 8.. zero d_cnt (+ d_stat in block 8)
// ---------------------------------------------------------------------------
__global__ void prep_kernel(const float* __restrict__ W) {
    int b = blockIdx.x, tid = threadIdx.x;
    if (b < 8) {
        int i = b * 1024 + tid;            // 8192 items
        int n = i >> 6, kp = i & 63;
        float w0 = W[(2 * kp)     * FE + n];
        float w1 = W[(2 * kp + 1) * FE + n];
        uint32_t hi, lo;
        split_pair(w0, w1, hi, lo);
        d_Wh[i] = hi;
        d_Wl[i] = lo;
    } else {
        if (b == 8 && tid < 64) d_stat[tid] = 0;
        int i = (b - 8) * 1024 + tid;
        if (i < NN) d_cnt[i] = 0;
    }
}

// ---------------------------------------------------------------------------
// hist: 8 edges / thread (MLP)
// ---------------------------------------------------------------------------
__global__ void hist_kernel(const int* __restrict__ edst) {
    int i = blockIdx.x * blockDim.x + threadIdx.x;
    if (i < NE / 8) {
        int4 a = ((const int4*)edst)[2 * i];
        int4 b = ((const int4*)edst)[2 * i + 1];
        atomicAdd(&d_cnt[a.x], 1); atomicAdd(&d_cnt[a.y], 1);
        atomicAdd(&d_cnt[a.z], 1); atomicAdd(&d_cnt[a.w], 1);
        atomicAdd(&d_cnt[b.x], 1); atomicAdd(&d_cnt[b.y], 1);
        atomicAdd(&d_cnt[b.z], 1); atomicAdd(&d_cnt[b.w], 1);
    }
}

// ---------------------------------------------------------------------------
// Single-pass decoupled-lookback exclusive scan: d_cnt -> d_off, d_cur.
// 49 blocks, all resident concurrently (<=148 SMs) so spinning is safe.
// ---------------------------------------------------------------------------
__global__ __launch_bounds__(1024)
void scan_kernel() {
    __shared__ int wsum[32];
    __shared__ int s_total;
    __shared__ int s_prefix;
    const int tid = threadIdx.x, lane = tid & 31, wid = tid >> 5;
    const int b = blockIdx.x;
    const int i = b * 1024 + tid;

    int x = (i < NN) ? d_cnt[i] : 0;
    int v = x;
    #pragma unroll
    for (int o = 1; o < 32; o <<= 1) {
        int t = __shfl_up_sync(0xffffffffu, v, o);
        if (lane >= o) v += t;
    }
    if (lane == 31) wsum[wid] = v;
    __syncthreads();
    if (tid < 32) {
        int s = wsum[tid];
        int sv = s;
        #pragma unroll
        for (int o = 1; o < 32; o <<= 1) {
            int t = __shfl_up_sync(0xffffffffu, sv, o);
            if (tid >= o) sv += t;
        }
        wsum[tid] = sv - s;                 // exclusive warp prefix
        if (tid == 31) s_total = sv;        // block total
    }
    __syncthreads();

    if (wid == 0) {
        int total = s_total;
        if (b == 0) {
            if (lane == 0) {
                atomicExch(&d_stat[0], PFLAG | total);
                s_prefix = 0;
            }
        } else {
            if (lane == 0) atomicExch(&d_stat[b], AFLAG | total);
            int run = 0, base = b - 1;
            for (;;) {
                int idx = base - lane;
                int s = 0;
                if (idx >= 0) {
                    do { s = atomicOr(&d_stat[idx], 0); } while (s == 0);
                }
                unsigned pm = __ballot_sync(0xffffffffu, idx >= 0 && (s & PFLAG));
                int lim = pm ? (__ffs(pm) - 1) : 31;
                int contrib = (idx >= 0 && lane <= lim) ? (s & VMASK) : 0;
                #pragma unroll
                for (int o = 16; o > 0; o >>= 1)
                    contrib += __shfl_down_sync(0xffffffffu, contrib, o);
                run += __shfl_sync(0xffffffffu, contrib, 0);
                if (pm) break;
                base -= 32;
            }
            if (lane == 0) {
                atomicExch(&d_stat[b], PFLAG | (run + total));
                s_prefix = run;
            }
        }
    }
    __syncthreads();

    int off = s_prefix + wsum[wid] + (v - x);
    if (i < NN) { d_off[i] = off; d_cur[i] = off; }
}

// ---------------------------------------------------------------------------
// fill: 8 edges / thread
// ---------------------------------------------------------------------------
__global__ void fill_kernel(const int* __restrict__ edst,
                            const int* __restrict__ esrc) {
    int i = blockIdx.x * blockDim.x + threadIdx.x;
    if (i < NE / 8) {
        int4 da = ((const int4*)edst)[2 * i];
        int4 db = ((const int4*)edst)[2 * i + 1];
        int4 sa = ((const int4*)esrc)[2 * i];
        int4 sb = ((const int4*)esrc)[2 * i + 1];
        d_srcl[atomicAdd(&d_cur[da.x], 1)] = sa.x;
        d_srcl[atomicAdd(&d_cur[da.y], 1)] = sa.y;
        d_srcl[atomicAdd(&d_cur[da.z], 1)] = sa.z;
        d_srcl[atomicAdd(&d_cur[da.w], 1)] = sa.w;
        d_srcl[atomicAdd(&d_cur[db.x], 1)] = sb.x;
        d_srcl[atomicAdd(&d_cur[db.y], 1)] = sb.y;
        d_srcl[atomicAdd(&d_cur[db.z], 1)] = sb.z;
        d_srcl[atomicAdd(&d_cur[db.w], 1)] = sb.w;
    }
}

// ---------------------------------------------------------------------------
// GEMM via mma.sync bf16 3-term split. 256 thr (8 warps), 128-row tile.
// Warp tiling 4x2: warp owns 32 rows x 64 cols (2 m16 tiles x 8 n8 blocks)
// -> fewer SMEM fragment loads per MMA than the 1x8 tiling.
// ---------------------------------------------------------------------------
#define XH_OFF 0
#define XL_OFF 8704
#define WH_OFF 17408
#define WL_OFF 26112
#define SM_U32 34816
#define SM_BYTES (SM_U32 * 4)

__global__ __launch_bounds__(256, 1)
void gemm_tc_kernel(const float* __restrict__ X, float* __restrict__ out) {
    extern __shared__ uint32_t smu[];
    const int tid  = threadIdx.x;
    const int wid  = tid >> 5, lane = tid & 31;
    const int g    = lane >> 2, tig = lane & 3;
    const int row0 = blockIdx.x * GT;

    // Stage W images (8192 u32 each) as uint4
    {
        const uint4* gh = (const uint4*)d_Wh;
        const uint4* gl = (const uint4*)d_Wl;
        #pragma unroll
        for (int i = 0; i < 8; ++i) {
            int q  = i * 256 + tid;          // 2048 uint4
            int n  = q >> 4, kq = q & 15;
            uint32_t o = n * ST + kq * 4;
            *(uint4*)&smu[WH_OFF + o] = gh[q];
            *(uint4*)&smu[WL_OFF + o] = gl[q];
        }
    }
    // Stage X tile: load fp32, split to bf16 hi/lo pairs
    #pragma unroll
    for (int i = 0; i < 16; ++i) {
        int q  = i * 256 + tid;              // 4096 float4
        int r  = q >> 5, c4 = q & 31;
        float4 v = make_float4(0.f, 0.f, 0.f, 0.f);
        if (row0 + r < NN) v = ((const float4*)X)[(size_t)(row0 + r) * 32 + c4];
        uint32_t h01, l01, h23, l23;
        split_pair(v.x, v.y, h01, l01);
        split_pair(v.z, v.w, h23, l23);
        uint32_t o = r * ST + c4 * 2;
        smu[XH_OFF + o]     = h01;
        smu[XH_OFF + o + 1] = h23;
        smu[XL_OFF + o]     = l01;
        smu[XL_OFF + o + 1] = l23;
    }
    __syncthreads();

    const int rw = (wid & 3) * 32;   // 4 m-groups of 32 rows
    const int cw = (wid >> 2) * 64;  // 2 n-groups of 64 cols

    float acc[2][8][4];
    #pragma unroll
    for (int t = 0; t < 2; ++t)
        #pragma unroll
        for (int j = 0; j < 8; ++j)
            #pragma unroll
            for (int q = 0; q < 4; ++q) acc[t][j][q] = 0.f;

    #pragma unroll
    for (int ks = 0; ks < 8; ++ks) {
        const int kb = ks * 8;
        uint32_t ah[2][4], al[2][4];
        #pragma unroll
        for (int t = 0; t < 2; ++t) {
            uint32_t r0 = (rw + t * 16 + g) * ST + kb + tig;
            uint32_t r8 = r0 + 8 * ST;
            ah[t][0] = smu[XH_OFF + r0];
            ah[t][1] = smu[XH_OFF + r8];
            ah[t][2] = smu[XH_OFF + r0 + 4];
            ah[t][3] = smu[XH_OFF + r8 + 4];
            al[t][0] = smu[XL_OFF + r0];
            al[t][1] = smu[XL_OFF + r8];
            al[t][2] = smu[XL_OFF + r0 + 4];
            al[t][3] = smu[XL_OFF + r8 + 4];
        }
        #pragma unroll
        for (int j = 0; j < 8; ++j) {
            uint32_t bo  = (cw + j * 8 + g) * ST + kb + tig;
            uint32_t bh0 = smu[WH_OFF + bo];
            uint32_t bh1 = smu[WH_OFF + bo + 4];
            uint32_t bl0 = smu[WL_OFF + bo];
            uint32_t bl1 = smu[WL_OFF + bo + 4];
            #pragma unroll
            for (int t = 0; t < 2; ++t) {
                mma16816(acc[t][j], ah[t][0], ah[t][1], ah[t][2], ah[t][3], bh0, bh1);
                mma16816(acc[t][j], ah[t][0], ah[t][1], ah[t][2], ah[t][3], bl0, bl1);
                mma16816(acc[t][j], al[t][0], al[t][1], al[t][2], al[t][3], bh0, bh1);
            }
        }
    }

    // Epilogue: Y -> scratch, relu(Y) -> out[:, 0:128]
    #pragma unroll
    for (int t = 0; t < 2; ++t) {
        #pragma unroll
        for (int j = 0; j < 8; ++j) {
            int col = cw + j * 8 + tig * 2;
            #pragma unroll
            for (int h = 0; h < 2; ++h) {
                int r = row0 + rw + t * 16 + g + h * 8;
                if (r < NN) {
                    float y0 = acc[t][j][h * 2], y1 = acc[t][j][h * 2 + 1];
                    *(float2*)&d_Y[(size_t)r * FE + col] = make_float2(y0, y1);
                    *(float2*)&out[(size_t)r * 256 + col] =
                        make_float2(fmaxf(y0, 0.f), fmaxf(y1, 0.f));
                }
            }
        }
    }
}

// ---------------------------------------------------------------------------
// Atomic-free aggregation: one warp per dst node
// ---------------------------------------------------------------------------
__global__ __launch_bounds__(256)
void agg_kernel(float* __restrict__ out) {
    int g    = blockIdx.x * blockDim.x + threadIdx.x;
    int n    = g >> 5;
    int lane = g & 31;
    if (n >= NN) return;

    int deg  = d_cnt[n];
    int base = d_off[n];
    float4 acc = make_float4(0.f, 0.f, 0.f, 0.f);

    int i = 0;
    for (; i + 4 <= deg; i += 4) {
        int s0 = d_srcl[base + i + 0];
        int s1 = d_srcl[base + i + 1];
        int s2 = d_srcl[base + i + 2];
        int s3 = d_srcl[base + i + 3];
        float4 v0 = ((const float4*)(d_Y + (size_t)s0 * FE))[lane];
        float4 v1 = ((const float4*)(d_Y + (size_t)s1 * FE))[lane];
        float4 v2 = ((const float4*)(d_Y + (size_t)s2 * FE))[lane];
        float4 v3 = ((const float4*)(d_Y + (size_t)s3 * FE))[lane];
        acc.x += v0.x + v1.x + v2.x + v3.x;
        acc.y += v0.y + v1.y + v2.y + v3.y;
        acc.z += v0.z + v1.z + v2.z + v3.z;
        acc.w += v0.w + v1.w + v2.w + v3.w;
    }
    for (; i < deg; ++i) {
        int s = d_srcl[base + i];
        float4 v = ((const float4*)(d_Y + (size_t)s * FE))[lane];
        acc.x += v.x; acc.y += v.y; acc.z += v.z; acc.w += v.w;
    }

    float inv = (deg > 0) ? (1.0f / (float)deg) : 0.0f;
    float4 r = make_float4(fmaxf(acc.x * inv, 0.f), fmaxf(acc.y * inv, 0.f),
                           fmaxf(acc.z * inv, 0.f), fmaxf(acc.w * inv, 0.f));
    ((float4*)(out + (size_t)n * 256 + 128))[lane] = r;
}

// ---------------------------------------------------------------------------
extern "C" void kernel_launch(void* const* d_in, const int* in_sizes, int n_in,
                              void* d_out, int out_size) {
    const float* X    = (const float*)d_in[0];
    const float* W    = (const float*)d_in[1];
    const int*   edst = (const int*)d_in[2];
    const int*   esrc = (const int*)d_in[3];
    float*       out  = (float*)d_out;

    cudaFuncSetAttribute(gemm_tc_kernel,
                         cudaFuncAttributeMaxDynamicSharedMemorySize, SM_BYTES);

    prep_kernel<<<8 + NSCAN, 1024>>>(W);
    hist_kernel<<<(NE / 8 + 255) / 256, 256>>>(edst);
    scan_kernel<<<NSCAN, 1024>>>();
    fill_kernel<<<(NE / 8 + 255) / 256, 256>>>(edst, esrc);
    gemm_tc_kernel<<<(NN + GT - 1) / GT, 256, SM_BYTES>>>(X, out);
    agg_kernel<<<(NN * 32 + 255) / 256, 256>>>(out);
}

// round 6
// speedup vs baseline: 2.1878x; 1.0535x over previous
#include <cuda_runtime.h>
#include <cuda_bf16.h>
#include <cuda_fp16.h>
#include <cstdint>

#define NN 50000
#define FE 128
#define NE 640000
#define GT 128            // GEMM tile rows per CTA
#define ST 68             // padded SMEM row stride (u32 units) — conflict-free

#define NSCAN 49          // ceil(NN/1024)
#define PFLAG (1 << 25)
#define AFLAG (1 << 24)
#define VMASK 0x00FFFFFF

// ---------------------------------------------------------------------------
// Scratch (__device__ globals: allocation-free rule)
// ---------------------------------------------------------------------------
__device__ __half   d_Yh[(size_t)NN * FE];  // X @ W (fp16, gather operand)
__device__ int      d_cnt[NN];              // in-degree
__device__ int      d_off[NN];              // CSR offsets
__device__ int      d_rank[NE];             // rank of edge within its dst bucket
__device__ int      d_srcl[NE];             // bucketed src ids
__device__ int      d_stat[64];             // lookback scan status
__device__ uint32_t d_Wh[FE * (FE / 2)];    // W^T bf16-hi k-pairs
__device__ uint32_t d_Wl[FE * (FE / 2)];    // W^T bf16-lo k-pairs

// ---------------------------------------------------------------------------
__device__ __forceinline__ void split_pair(float f0, float f1,
                                           uint32_t& hi, uint32_t& lo) {
    __nv_bfloat162 h2 = __floats2bfloat162_rn(f0, f1);
    float h0 = __bfloat162float(h2.x), h1 = __bfloat162float(h2.y);
    __nv_bfloat162 l2 = __floats2bfloat162_rn(f0 - h0, f1 - h1);
    hi = *(uint32_t*)&h2;
    lo = *(uint32_t*)&l2;
}

__device__ __forceinline__ void mma16816(float* c,
                                         uint32_t a0, uint32_t a1, uint32_t a2, uint32_t a3,
                                         uint32_t b0, uint32_t b1) {
    asm volatile(
        "mma.sync.aligned.m16n8k16.row.col.f32.bf16.bf16.f32 "
        "{%0,%1,%2,%3}, {%4,%5,%6,%7}, {%8,%9}, {%0,%1,%2,%3};"
        : "+f"(c[0]), "+f"(c[1]), "+f"(c[2]), "+f"(c[3])
        : "r"(a0), "r"(a1), "r"(a2), "r"(a3), "r"(b0), "r"(b1));
}

// ---------------------------------------------------------------------------
// prep: blocks 0..7 convert W; blocks 8.. zero d_cnt (+ d_stat in block 8)
// ---------------------------------------------------------------------------
__global__ void prep_kernel(const float* __restrict__ W) {
    int b = blockIdx.x, tid = threadIdx.x;
    if (b < 8) {
        int i = b * 1024 + tid;            // 8192 items
        int n = i >> 6, kp = i & 63;
        float w0 = W[(2 * kp)     * FE + n];
        float w1 = W[(2 * kp + 1) * FE + n];
        uint32_t hi, lo;
        split_pair(w0, w1, hi, lo);
        d_Wh[i] = hi;
        d_Wl[i] = lo;
    } else {
        if (b == 8 && tid < 64) d_stat[tid] = 0;
        int i = (b - 8) * 1024 + tid;
        if (i < NN) d_cnt[i] = 0;
    }
}

// ---------------------------------------------------------------------------
// hist: 8 edges / thread; atomic RETURN VALUE = rank of edge in its bucket
// ---------------------------------------------------------------------------
__global__ void hist_kernel(const int* __restrict__ edst) {
    int i = blockIdx.x * blockDim.x + threadIdx.x;
    if (i < NE / 8) {
        int4 a = ((const int4*)edst)[2 * i];
        int4 b = ((const int4*)edst)[2 * i + 1];
        int4 ra, rb;
        ra.x = atomicAdd(&d_cnt[a.x], 1);
        ra.y = atomicAdd(&d_cnt[a.y], 1);
        ra.z = atomicAdd(&d_cnt[a.z], 1);
        ra.w = atomicAdd(&d_cnt[a.w], 1);
        rb.x = atomicAdd(&d_cnt[b.x], 1);
        rb.y = atomicAdd(&d_cnt[b.y], 1);
        rb.z = atomicAdd(&d_cnt[b.z], 1);
        rb.w = atomicAdd(&d_cnt[b.w], 1);
        ((int4*)d_rank)[2 * i]     = ra;
        ((int4*)d_rank)[2 * i + 1] = rb;
    }
}

// ---------------------------------------------------------------------------
// Single-pass decoupled-lookback exclusive scan: d_cnt -> d_off.
// 49 blocks, all resident concurrently, spinning is safe.
// ---------------------------------------------------------------------------
__global__ __launch_bounds__(1024)
void scan_kernel() {
    __shared__ int wsum[32];
    __shared__ int s_total;
    __shared__ int s_prefix;
    const int tid = threadIdx.x, lane = tid & 31, wid = tid >> 5;
    const int b = blockIdx.x;
    const int i = b * 1024 + tid;

    int x = (i < NN) ? d_cnt[i] : 0;
    int v = x;
    #pragma unroll
    for (int o = 1; o < 32; o <<= 1) {
        int t = __shfl_up_sync(0xffffffffu, v, o);
        if (lane >= o) v += t;
    }
    if (lane == 31) wsum[wid] = v;
    __syncthreads();
    if (tid < 32) {
        int s = wsum[tid];
        int sv = s;
        #pragma unroll
        for (int o = 1; o < 32; o <<= 1) {
            int t = __shfl_up_sync(0xffffffffu, sv, o);
            if (tid >= o) sv += t;
        }
        wsum[tid] = sv - s;
        if (tid == 31) s_total = sv;
    }
    __syncthreads();

    if (wid == 0) {
        int total = s_total;
        if (b == 0) {
            if (lane == 0) {
                atomicExch(&d_stat[0], PFLAG | total);
                s_prefix = 0;
            }
        } else {
            if (lane == 0) atomicExch(&d_stat[b], AFLAG | total);
            int run = 0, base = b - 1;
            for (;;) {
                int idx = base - lane;
                int s = 0;
                if (idx >= 0) {
                    do { s = atomicOr(&d_stat[idx], 0); } while (s == 0);
                }
                unsigned pm = __ballot_sync(0xffffffffu, idx >= 0 && (s & PFLAG));
                int lim = pm ? (__ffs(pm) - 1) : 31;
                int contrib = (idx >= 0 && lane <= lim) ? (s & VMASK) : 0;
                #pragma unroll
                for (int o = 16; o > 0; o >>= 1)
                    contrib += __shfl_down_sync(0xffffffffu, contrib, o);
                run += __shfl_sync(0xffffffffu, contrib, 0);
                if (pm) break;
                base -= 32;
            }
            if (lane == 0) {
                atomicExch(&d_stat[b], PFLAG | (run + total));
                s_prefix = run;
            }
        }
    }
    __syncthreads();

    int off = s_prefix + wsum[wid] + (v - x);
    if (i < NN) d_off[i] = off;
}

// ---------------------------------------------------------------------------
// fill: ATOMIC-FREE — slot = off[dst] + rank[e]
// ---------------------------------------------------------------------------
__global__ void fill_kernel(const int* __restrict__ edst,
                            const int* __restrict__ esrc) {
    int i = blockIdx.x * blockDim.x + threadIdx.x;
    if (i < NE / 4) {
        int4 d = ((const int4*)edst)[i];
        int4 s = ((const int4*)esrc)[i];
        int4 r = ((const int4*)d_rank)[i];
        d_srcl[d_off[d.x] + r.x] = s.x;
        d_srcl[d_off[d.y] + r.y] = s.y;
        d_srcl[d_off[d.z] + r.z] = s.z;
        d_srcl[d_off[d.w] + r.w] = s.w;
    }
}

// ---------------------------------------------------------------------------
// GEMM via mma.sync bf16 3-term split. 256 thr (8 warps), 128-row tile,
// 4x2 warp tiling. Epilogue: Y -> fp16 scratch, relu(Y) -> out[:, 0:128].
// ---------------------------------------------------------------------------
#define XH_OFF 0
#define XL_OFF 8704
#define WH_OFF 17408
#define WL_OFF 26112
#define SM_U32 34816
#define SM_BYTES (SM_U32 * 4)

__global__ __launch_bounds__(256, 1)
void gemm_tc_kernel(const float* __restrict__ X, float* __restrict__ out) {
    extern __shared__ uint32_t smu[];
    const int tid  = threadIdx.x;
    const int wid  = tid >> 5, lane = tid & 31;
    const int g    = lane >> 2, tig = lane & 3;
    const int row0 = blockIdx.x * GT;

    {
        const uint4* gh = (const uint4*)d_Wh;
        const uint4* gl = (const uint4*)d_Wl;
        #pragma unroll
        for (int i = 0; i < 8; ++i) {
            int q  = i * 256 + tid;
            int n  = q >> 4, kq = q & 15;
            uint32_t o = n * ST + kq * 4;
            *(uint4*)&smu[WH_OFF + o] = gh[q];
            *(uint4*)&smu[WL_OFF + o] = gl[q];
        }
    }
    #pragma unroll
    for (int i = 0; i < 16; ++i) {
        int q  = i * 256 + tid;
        int r  = q >> 5, c4 = q & 31;
        float4 v = make_float4(0.f, 0.f, 0.f, 0.f);
        if (row0 + r < NN) v = ((const float4*)X)[(size_t)(row0 + r) * 32 + c4];
        uint32_t h01, l01, h23, l23;
        split_pair(v.x, v.y, h01, l01);
        split_pair(v.z, v.w, h23, l23);
        uint32_t o = r * ST + c4 * 2;
        smu[XH_OFF + o]     = h01;
        smu[XH_OFF + o + 1] = h23;
        smu[XL_OFF + o]     = l01;
        smu[XL_OFF + o + 1] = l23;
    }
    __syncthreads();

    const int rw = (wid & 3) * 32;
    const int cw = (wid >> 2) * 64;

    float acc[2][8][4];
    #pragma unroll
    for (int t = 0; t < 2; ++t)
        #pragma unroll
        for (int j = 0; j < 8; ++j)
            #pragma unroll
            for (int q = 0; q < 4; ++q) acc[t][j][q] = 0.f;

    #pragma unroll
    for (int ks = 0; ks < 8; ++ks) {
        const int kb = ks * 8;
        uint32_t ah[2][4], al[2][4];
        #pragma unroll
        for (int t = 0; t < 2; ++t) {
            uint32_t r0 = (rw + t * 16 + g) * ST + kb + tig;
            uint32_t r8 = r0 + 8 * ST;
            ah[t][0] = smu[XH_OFF + r0];
            ah[t][1] = smu[XH_OFF + r8];
            ah[t][2] = smu[XH_OFF + r0 + 4];
            ah[t][3] = smu[XH_OFF + r8 + 4];
            al[t][0] = smu[XL_OFF + r0];
            al[t][1] = smu[XL_OFF + r8];
            al[t][2] = smu[XL_OFF + r0 + 4];
            al[t][3] = smu[XL_OFF + r8 + 4];
        }
        #pragma unroll
        for (int j = 0; j < 8; ++j) {
            uint32_t bo  = (cw + j * 8 + g) * ST + kb + tig;
            uint32_t bh0 = smu[WH_OFF + bo];
            uint32_t bh1 = smu[WH_OFF + bo + 4];
            uint32_t bl0 = smu[WL_OFF + bo];
            uint32_t bl1 = smu[WL_OFF + bo + 4];
            #pragma unroll
            for (int t = 0; t < 2; ++t) {
                mma16816(acc[t][j], ah[t][0], ah[t][1], ah[t][2], ah[t][3], bh0, bh1);
                mma16816(acc[t][j], ah[t][0], ah[t][1], ah[t][2], ah[t][3], bl0, bl1);
                mma16816(acc[t][j], al[t][0], al[t][1], al[t][2], al[t][3], bh0, bh1);
            }
        }
    }

    #pragma unroll
    for (int t = 0; t < 2; ++t) {
        #pragma unroll
        for (int j = 0; j < 8; ++j) {
            int col = cw + j * 8 + tig * 2;
            #pragma unroll
            for (int h = 0; h < 2; ++h) {
                int r = row0 + rw + t * 16 + g + h * 8;
                if (r < NN) {
                    float y0 = acc[t][j][h * 2], y1 = acc[t][j][h * 2 + 1];
                    *(__half2*)&d_Yh[(size_t)r * FE + col] =
                        __float22half2_rn(make_float2(y0, y1));
                    *(float2*)&out[(size_t)r * 256 + col] =
                        make_float2(fmaxf(y0, 0.f), fmaxf(y1, 0.f));
                }
            }
        }
    }
}

// ---------------------------------------------------------------------------
// Atomic-free aggregation: one warp per dst node; fp16 gather, fp32 accum.
// Lane l covers columns 4l..4l+3 (one uint2 = 4 halves per row).
// ---------------------------------------------------------------------------
__global__ __launch_bounds__(256)
void agg_kernel(float* __restrict__ out) {
    int g    = blockIdx.x * blockDim.x + threadIdx.x;
    int n    = g >> 5;
    int lane = g & 31;
    if (n >= NN) return;

    int deg  = d_cnt[n];
    int base = d_off[n];
    float4 acc = make_float4(0.f, 0.f, 0.f, 0.f);

    int i = 0;
    for (; i + 4 <= deg; i += 4) {
        int s0 = d_srcl[base + i + 0];
        int s1 = d_srcl[base + i + 1];
        int s2 = d_srcl[base + i + 2];
        int s3 = d_srcl[base + i + 3];
        uint2 u0 = ((const uint2*)(d_Yh + (size_t)s0 * FE))[lane];
        uint2 u1 = ((const uint2*)(d_Yh + (size_t)s1 * FE))[lane];
        uint2 u2 = ((const uint2*)(d_Yh + (size_t)s2 * FE))[lane];
        uint2 u3 = ((const uint2*)(d_Yh + (size_t)s3 * FE))[lane];
        float2 a0 = __half22float2(*(__half2*)&u0.x), b0 = __half22float2(*(__half2*)&u0.y);
        float2 a1 = __half22float2(*(__half2*)&u1.x), b1 = __half22float2(*(__half2*)&u1.y);
        float2 a2 = __half22float2(*(__half2*)&u2.x), b2 = __half22float2(*(__half2*)&u2.y);
        float2 a3 = __half22float2(*(__half2*)&u3.x), b3 = __half22float2(*(__half2*)&u3.y);
        acc.x += (a0.x + a1.x) + (a2.x + a3.x);
        acc.y += (a0.y + a1.y) + (a2.y + a3.y);
        acc.z += (b0.x + b1.x) + (b2.x + b3.x);
        acc.w += (b0.y + b1.y) + (b2.y + b3.y);
    }
    for (; i < deg; ++i) {
        int s = d_srcl[base + i];
        uint2 u = ((const uint2*)(d_Yh + (size_t)s * FE))[lane];
        float2 a = __half22float2(*(__half2*)&u.x), b = __half22float2(*(__half2*)&u.y);
        acc.x += a.x; acc.y += a.y; acc.z += b.x; acc.w += b.y;
    }

    float inv = (deg > 0) ? (1.0f / (float)deg) : 0.0f;
    float4 r = make_float4(fmaxf(acc.x * inv, 0.f), fmaxf(acc.y * inv, 0.f),
                           fmaxf(acc.z * inv, 0.f), fmaxf(acc.w * inv, 0.f));
    ((float4*)(out + (size_t)n * 256 + 128))[lane] = r;
}

// ---------------------------------------------------------------------------
extern "C" void kernel_launch(void* const* d_in, const int* in_sizes, int n_in,
                              void* d_out, int out_size) {
    const float* X    = (const float*)d_in[0];
    const float* W    = (const float*)d_in[1];
    const int*   edst = (const int*)d_in[2];
    const int*   esrc = (const int*)d_in[3];
    float*       out  = (float*)d_out;

    cudaFuncSetAttribute(gemm_tc_kernel,
                         cudaFuncAttributeMaxDynamicSharedMemorySize, SM_BYTES);

    prep_kernel<<<8 + NSCAN, 1024>>>(W);
    hist_kernel<<<(NE / 8 + 255) / 256, 256>>>(edst);
    scan_kernel<<<NSCAN, 1024>>>();
    fill_kernel<<<(NE / 4 + 255) / 256, 256>>>(edst, esrc);
    gemm_tc_kernel<<<(NN + GT - 1) / GT, 256, SM_BYTES>>>(X, out);
    agg_kernel<<<(NN * 32 + 255) / 256, 256>>>(out);
}